// round 1
// baseline (speedup 1.0000x reference)
#include <cuda_runtime.h>
#include <math.h>

#define BB 1024
#define TT 128
#define KK 128
#define STARTT 126
#define STOPP 127

// Shared memory layout (bytes):
//   [0, 65536)        trT   : transposed+swizzled transitions, float[128*128]
//   [65536, 66560)    part  : double-buffered partition, float[2][128]
//   [66560, 67072)    finv  : final values for STOP reduction, float[128]
//   [67072, 67584)    dec   : decoded tags, int[128]
//   [67584, 67616)    misc  : int[8] (len partials, pointer, score bits)
//   [67616, 84000)    bp    : backpointers uint8[128][128]
#define SMEM_BYTES 84000

__device__ __forceinline__ void process4(const float4* __restrict__ trow,
                                         const float4* __restrict__ pp,
                                         int c, int cx,
                                         float& best, int& bi) {
    // memory chunk (c ^ cx) holds prev-group c (swizzle), conflict-free LDS.128
    float4 tv = trow[c ^ cx];
    float4 pv = pp[c];           // broadcast across lanes
    float v;
    float nb;
    v = pv.x + tv.x; nb = fmaxf(best, v); bi = (v > best) ? (c * 4 + 0) : bi; best = nb;
    v = pv.y + tv.y; nb = fmaxf(best, v); bi = (v > best) ? (c * 4 + 1) : bi; best = nb;
    v = pv.z + tv.z; nb = fmaxf(best, v); bi = (v > best) ? (c * 4 + 2) : bi; best = nb;
    v = pv.w + tv.w; nb = fmaxf(best, v); bi = (v > best) ? (c * 4 + 3) : bi; best = nb;
}

__global__ __launch_bounds__(128, 2)
void viterbi_kernel(const float* __restrict__ feats,
                    const float* __restrict__ trans,
                    const void*  __restrict__ masks,
                    float* __restrict__ out,
                    int score_off, int dec_off)
{
    extern __shared__ unsigned char sm[];
    float*         trT  = (float*)(sm);
    float*         part = (float*)(sm + 65536);
    float*         finv = (float*)(sm + 66560);
    int*           dec  = (int*)  (sm + 67072);
    int*           misc = (int*)  (sm + 67584);
    unsigned char* bp   = sm + 67616;

    const int b   = blockIdx.x;
    const int tid = threadIdx.x;

    // ---- Stage transitions into SMEM, transposed with chunk-XOR swizzle ----
    // trT(cur, prev) stored at float index cur*128 + ((((prev>>2)^(cur&7))<<2) | (prev&3))
    #pragma unroll 4
    for (int i = tid; i < KK * KK; i += 128) {
        int prev = i >> 7;
        int cur  = i & 127;
        int w = (cur << 7) + ((((prev >> 2) ^ (cur & 7)) << 2) | (prev & 3));
        trT[w] = trans[i];
    }

    // ---- Sequence length (mask dtype auto-detected from first word) ----
    unsigned w0 = *(const unsigned*)masks;   // masks[0][0] is always true (len >= T/2)
    int m;
    if (w0 == 1u) {                 // int32 0/1
        m = ((const int*)masks)[b * TT + tid] != 0;
    } else if (w0 == 0x3F800000u) { // float32 0/1
        m = (((const float*)masks)[b * TT + tid] != 0.0f);
    } else {                        // int8 / bool bytes
        m = ((const unsigned char*)masks)[b * TT + tid] != 0;
    }
    unsigned bal = __ballot_sync(0xffffffffu, m);
    if ((tid & 31) == 0) misc[tid >> 5] = __popc(bal);
    __syncthreads();
    const int len = misc[0] + misc[1] + misc[2] + misc[3];

    const float* fb = feats + (size_t)b * (TT * KK);

    // ---- t = 0 init: part[cur] = feat0[cur] + trans[START, cur] ----
    {
        // trT(cur=tid, prev=START=126): chunk = (126>>2)^(tid&7) = 31^(tid&7), word = 2
        int w = (tid << 7) + (((31 ^ (tid & 7)) << 2) | 2);
        part[tid] = fb[tid] + trT[w];
    }
    __syncthreads();

    const int cx = tid & 7;
    const float4* trow = (const float4*)(trT + (tid << 7));

    // ---- Forward Viterbi ----
    for (int t = 1; t < len; ++t) {
        const float4* pp = (const float4*)(part + (((t - 1) & 1) << 7));
        float ft = fb[t * KK + tid];  // prefetch

        // 4 contiguous accumulator ranges for ILP; contiguity preserves
        // first-index tie-break semantics on merge.
        float b0 = -INFINITY, b1 = -INFINITY, b2 = -INFINITY, b3 = -INFINITY;
        int i0 = 0, i1 = 0, i2 = 0, i3 = 0;
        #pragma unroll
        for (int c = 0; c < 8; ++c) {
            process4(trow, pp, c,      cx, b0, i0);
            process4(trow, pp, c + 8,  cx, b1, i1);
            process4(trow, pp, c + 16, cx, b2, i2);
            process4(trow, pp, c + 24, cx, b3, i3);
        }
        float best = b0; int bi = i0;
        if (b1 > best) { best = b1; bi = i1; }
        if (b2 > best) { best = b2; bi = i2; }
        if (b3 > best) { best = b3; bi = i3; }

        part[((t & 1) << 7) + tid] = best + ft;
        bp[(t << 7) + tid] = (unsigned char)bi;
        __syncthreads();
    }

    // ---- Transition to STOP from partition at last valid position ----
    {
        const float* lp = part + (((len - 1) & 1) << 7);
        // trT(cur=STOP=127, prev=tid): chunk = (tid>>2)^7, word = tid&3
        int w = (STOPP << 7) + ((((tid >> 2) ^ 7) << 2) | (tid & 3));
        finv[tid] = lp[tid] + trT[w];
    }
    __syncthreads();

    if (tid == 0) {
        float bsc = finv[0];
        int ptr = 0;
        #pragma unroll 4
        for (int p = 1; p < KK; ++p) {
            float v = finv[p];
            if (v > bsc) { bsc = v; ptr = p; }
        }
        misc[4] = ptr;
        misc[5] = __float_as_int(bsc);
        // Backtrace
        dec[len - 1] = ptr;
        int q = ptr;
        for (int t = len - 1; t >= 1; --t) {
            q = bp[(t << 7) + q];
            dec[t - 1] = q;
        }
    }
    __syncthreads();

    const int ptr = misc[4];
    const float score = __int_as_float(misc[5]);

    // decode_idx[b][t]: path tags for t < len, 0 for len <= t <= T-2, pointer at T-1
    int val;
    if (tid < len)          val = dec[tid];
    else if (tid == TT - 1) val = ptr;
    else                    val = 0;

    if (dec_off >= 0)  out[dec_off + b * TT + tid] = (float)val;
    if (score_off >= 0 && tid == 0) out[score_off + b] = score;
}

extern "C" void kernel_launch(void* const* d_in, const int* in_sizes, int n_in,
                              void* d_out, int out_size) {
    const float* feats = nullptr;
    const float* trans = nullptr;
    const void*  masks = nullptr;
    for (int i = 0; i < n_in; ++i) {
        if      (in_sizes[i] == BB * TT * KK) feats = (const float*)d_in[i];
        else if (in_sizes[i] == KK * KK)      trans = (const float*)d_in[i];
        else                                  masks = d_in[i];
    }

    int score_off, dec_off;
    if      (out_size == BB * TT + BB) { score_off = 0;  dec_off = BB; }
    else if (out_size == BB * TT)      { score_off = -1; dec_off = 0;  }
    else if (out_size == BB)           { score_off = 0;  dec_off = -1; }
    else                               { score_off = 0;  dec_off = BB; }

    cudaFuncSetAttribute(viterbi_kernel,
                         cudaFuncAttributeMaxDynamicSharedMemorySize, SMEM_BYTES);
    viterbi_kernel<<<BB, 128, SMEM_BYTES>>>(feats, trans, masks,
                                            (float*)d_out, score_off, dec_off);
}

// round 2
// speedup vs baseline: 1.5718x; 1.5718x over previous
#include <cuda_runtime.h>
#include <math.h>

#define BB 1024
#define TT 128
#define KK 128
#define STARTT 126
#define STOPP 127

typedef unsigned long long ull;

__device__ __forceinline__ ull addx2(ull a, ull b) {
    ull r;
    asm("add.rn.f32x2 %0, %1, %2;" : "=l"(r) : "l"(a), "l"(b));
    return r;
}
__device__ __forceinline__ float lo32(ull v) { return __uint_as_float((unsigned)v); }
__device__ __forceinline__ float hi32(ull v) { return __uint_as_float((unsigned)(v >> 32)); }
__device__ __forceinline__ ull packf2(float lo, float hi) {
    ull r;
    asm("mov.b64 %0, {%1, %2};" : "=l"(r) : "r"(__float_as_uint(lo)), "r"(__float_as_uint(hi)));
    return r;
}

__global__ __launch_bounds__(128, 2)
void viterbi_kernel(const float* __restrict__ feats,
                    const float* __restrict__ trans,
                    const void*  __restrict__ masks,
                    float* __restrict__ out,
                    int score_off, int dec_off)
{
    __shared__ __align__(16) float part[2][KK];
    __shared__ float finv[KK];
    __shared__ int   dec_s[TT];
    __shared__ int   misc[8];
    __shared__ unsigned char bp[TT * KK];

    const int b   = blockIdx.x;
    const int tid = threadIdx.x;

    // ---- trans column for this cur tag into 64 packed-f32x2 registers ----
    // tv2[k] = pack(trans[2k][tid], trans[2k+1][tid]); LDGs coalesced across lanes.
    ull tv2[64];
    #pragma unroll
    for (int k = 0; k < 64; ++k) {
        float lo = trans[(2 * k)     * KK + tid];
        float hi = trans[(2 * k + 1) * KK + tid];
        tv2[k] = packf2(lo, hi);
    }

    // ---- sequence length (mask dtype auto-detected) ----
    unsigned w0 = *(const unsigned*)masks;
    int m;
    if (w0 == 1u) {
        m = ((const int*)masks)[b * TT + tid] != 0;
    } else if (w0 == 0x3F800000u) {
        m = (((const float*)masks)[b * TT + tid] != 0.0f);
    } else {
        m = ((const unsigned char*)masks)[b * TT + tid] != 0;
    }
    unsigned bal = __ballot_sync(0xffffffffu, m);
    if ((tid & 31) == 0) misc[tid >> 5] = __popc(bal);
    __syncthreads();
    const int len = misc[0] + misc[1] + misc[2] + misc[3];

    const float* fb = feats + (size_t)b * (TT * KK);

    // ---- t = 0 init ----
    part[0][tid] = fb[tid] + trans[STARTT * KK + tid];
    __syncthreads();

    // ---- Forward Viterbi ----
    for (int t = 1; t < len; ++t) {
        const float* pp = part[(t - 1) & 1];
        const ulonglong2* pp2 = (const ulonglong2*)pp;   // broadcast LDS.128
        float ft = fb[t * KK + tid];                     // prefetch

        // Phase 1: pure max sweep, 8 contiguous ranges of 16 prevs each.
        float a[8];
        #pragma unroll
        for (int r = 0; r < 8; ++r) {
            ulonglong2 u0 = pp2[r * 4 + 0];
            ulonglong2 u1 = pp2[r * 4 + 1];
            ulonglong2 u2 = pp2[r * 4 + 2];
            ulonglong2 u3 = pp2[r * 4 + 3];
            ull s0 = addx2(u0.x, tv2[r * 8 + 0]);
            ull s1 = addx2(u0.y, tv2[r * 8 + 1]);
            ull s2 = addx2(u1.x, tv2[r * 8 + 2]);
            ull s3 = addx2(u1.y, tv2[r * 8 + 3]);
            ull s4 = addx2(u2.x, tv2[r * 8 + 4]);
            ull s5 = addx2(u2.y, tv2[r * 8 + 5]);
            ull s6 = addx2(u3.x, tv2[r * 8 + 6]);
            ull s7 = addx2(u3.y, tv2[r * 8 + 7]);
            float m0 = fmaxf(fmaxf(lo32(s0), hi32(s0)), fmaxf(lo32(s1), hi32(s1)));
            float m1 = fmaxf(fmaxf(lo32(s2), hi32(s2)), fmaxf(lo32(s3), hi32(s3)));
            float m2 = fmaxf(fmaxf(lo32(s4), hi32(s4)), fmaxf(lo32(s5), hi32(s5)));
            float m3 = fmaxf(fmaxf(lo32(s6), hi32(s6)), fmaxf(lo32(s7), hi32(s7)));
            a[r] = fmaxf(fmaxf(m0, m1), fmaxf(m2, m3));
        }
        float best = fmaxf(fmaxf(fmaxf(a[0], a[1]), fmaxf(a[2], a[3])),
                           fmaxf(fmaxf(a[4], a[5]), fmaxf(a[6], a[7])));

        // First range whose max equals the global max contains the first argmax.
        int rsel = 7;
        #pragma unroll
        for (int r = 6; r >= 0; --r) rsel = (a[r] == best) ? r : rsel;

        // Phase 2: rescan the 16 prevs of rsel; recompute is bitwise-identical
        // (IEEE rn add of the same operand bits), so equality is guaranteed.
        int base = rsel << 4;
        const float* g0 = trans + (size_t)base * KK + tid;  // L1-hot column gather
        float vv[16];
        #pragma unroll
        for (int j = 0; j < 16; ++j) vv[j] = pp[base + j] + g0[j * KK];
        int idx = base;
        #pragma unroll
        for (int j = 15; j >= 0; --j) idx = (vv[j] == best) ? (base + j) : idx;

        part[t & 1][tid] = best + ft;
        bp[t * KK + tid] = (unsigned char)idx;
        __syncthreads();
    }

    // ---- Transition to STOP from the last valid partition ----
    {
        const float* lp = part[(len - 1) & 1];
        finv[tid] = lp[tid] + trans[tid * KK + STOPP];  // one-time stride gather
    }
    __syncthreads();

    if (tid == 0) {
        float bsc = finv[0];
        int ptr = 0;
        #pragma unroll 4
        for (int p = 1; p < KK; ++p) {
            float v = finv[p];
            if (v > bsc) { bsc = v; ptr = p; }
        }
        misc[4] = ptr;
        misc[5] = __float_as_int(bsc);
        dec_s[len - 1] = ptr;
        int q = ptr;
        for (int t = len - 1; t >= 1; --t) {
            q = bp[t * KK + q];
            dec_s[t - 1] = q;
        }
    }
    __syncthreads();

    const int ptr = misc[4];
    const float score = __int_as_float(misc[5]);

    int val;
    if (tid < len)          val = dec_s[tid];
    else if (tid == TT - 1) val = ptr;
    else                    val = 0;

    if (dec_off >= 0)  out[dec_off + b * TT + tid] = (float)val;
    if (score_off >= 0 && tid == 0) out[score_off + b] = score;
}

extern "C" void kernel_launch(void* const* d_in, const int* in_sizes, int n_in,
                              void* d_out, int out_size) {
    const float* feats = nullptr;
    const float* trans = nullptr;
    const void*  masks = nullptr;
    for (int i = 0; i < n_in; ++i) {
        if      (in_sizes[i] == BB * TT * KK) feats = (const float*)d_in[i];
        else if (in_sizes[i] == KK * KK)      trans = (const float*)d_in[i];
        else                                  masks = d_in[i];
    }

    int score_off, dec_off;
    if      (out_size == BB * TT + BB) { score_off = 0;  dec_off = BB; }
    else if (out_size == BB * TT)      { score_off = -1; dec_off = 0;  }
    else if (out_size == BB)           { score_off = 0;  dec_off = -1; }
    else                               { score_off = 0;  dec_off = BB; }

    viterbi_kernel<<<BB, 128>>>(feats, trans, masks,
                                (float*)d_out, score_off, dec_off);
}